// round 3
// baseline (speedup 1.0000x reference)
#include <cuda_runtime.h>
#include <cuda_bf16.h>

namespace {

constexpr int Dd = 160;
constexpr int Hh = 192;
constexpr int Ww = 224;
constexpr int HW = Hh * Ww;        // 43008
constexpr int N  = Dd * HW;        // 6881280

// tile config — static smem must stay <= 48KB so no cudaFuncSetAttribute is needed
constexpr int TD = 8, TH = 16, TW = 32;      // outputs per block (4096)
constexpr int M  = 3;                        // halo margin (N(0,1) jitter)
constexpr int SD = TD + 2 * M;               // 14
constexpr int SH = TH + 2 * M;               // 22
constexpr int SW = TW + 2 * M;               // 38
constexpr int SSLICE = SH * SW;              // 836
constexpr int STOT   = SD * SSLICE;          // 11704 floats = 46816 B
constexpr int NTHREADS = 256;

__global__ __launch_bounds__(NTHREADS)
void st3d_tiled_kernel(const float* __restrict__ img,   // (160,192,224) fp32
                       const float* __restrict__ off,   // (3,160,192,224) fp32
                       float* __restrict__ out)         // (160,192,224) fp32
{
    __shared__ float smem[STOT];      // 46816 B static — under 48KB limit

    const int tid  = threadIdx.x;
    const int lane = tid & 31;
    const int warp = tid >> 5;

    const int D0 = blockIdx.z * TD;
    const int H0 = blockIdx.y * TH;
    const int W0 = blockIdx.x * TW;
    const int d_org = D0 - M, h_org = H0 - M, w_org = W0 - M;

    // ---- stage input tile (+halo) into smem, coalesced, zero outside volume ----
    #pragma unroll 4
    for (int idx = tid; idx < STOT; idx += NTHREADS) {
        const int sd = idx / SSLICE;
        const int r  = idx - sd * SSLICE;
        const int sh = r / SW;
        const int sw = r - sh * SW;
        const int gd = d_org + sd;
        const int gh = h_org + sh;
        const int gw = w_org + sw;
        float v = 0.f;
        if ((unsigned)gd < (unsigned)Dd && (unsigned)gh < (unsigned)Hh &&
            (unsigned)gw < (unsigned)Ww)
            v = __ldg(img + gd * HW + gh * Ww + gw);
        smem[idx] = v;
    }
    __syncthreads();

    // ---- main loop: each warp handles (d,h) rows, lane = w within row ----
    #pragma unroll 2
    for (int rr = warp; rr < TD * TH; rr += NTHREADS / 32) {
        const int dl = rr >> 4;          // local d (TH = 16)
        const int hl = rr & 15;          // local h
        const int d = D0 + dl;
        const int h = H0 + hl;
        const int w = W0 + lane;
        const int g = d * HW + h * Ww + w;

        const float dDv = __ldg(off + g);
        const float dHv = __ldg(off + N + g);
        const float dWv = __ldg(off + 2 * N + g);

        // padded-space coords (reference adds +1 for the pad shift)
        const float Dup = dDv + (float)(d + 1);
        const float Hup = dHv + (float)(h + 1);
        const float Wup = dWv + (float)(w + 1);

        const int df = __float2int_rd(Dup);
        const int hf = __float2int_rd(Hup);
        const int wf = __float2int_rd(Wup);

        const float fd = Dup - (float)df;   // weight of the +1 tap per dim
        const float fh = Hup - (float)hf;
        const float fw = Wup - (float)wf;

        // data-space floor-tap indices
        const int d0 = df - 1, h0 = hf - 1, w0 = wf - 1;

        float v000 = 0.f, v001 = 0.f, v010 = 0.f, v011 = 0.f;
        float v100 = 0.f, v101 = 0.f, v110 = 0.f, v111 = 0.f;

        // staged-local coords
        const int sd0 = d0 - d_org;
        const int sh0 = h0 - h_org;
        const int sw0 = w0 - w_org;

        if ((unsigned)sd0 <= (unsigned)(SD - 2) &&
            (unsigned)sh0 <= (unsigned)(SH - 2) &&
            (unsigned)sw0 <= (unsigned)(SW - 2)) {
            // fast path: all 8 taps staged (volume boundary = zeros already)
            const float* ps = smem + (sd0 * SH + sh0) * SW + sw0;
            v000 = ps[0];
            v001 = ps[1];
            v010 = ps[SW];
            v011 = ps[SW + 1];
            v100 = ps[SSLICE];
            v101 = ps[SSLICE + 1];
            v110 = ps[SSLICE + SW];
            v111 = ps[SSLICE + SW + 1];
        } else {
            // rare fallback: tap escaped the halo — gather from global
            const bool pd0 = (unsigned)d0 < (unsigned)Dd;
            const bool pd1 = (unsigned)df < (unsigned)Dd;
            const bool ph0 = (unsigned)h0 < (unsigned)Hh;
            const bool ph1 = (unsigned)hf < (unsigned)Hh;
            const bool pw0 = (unsigned)w0 < (unsigned)Ww;
            const bool pw1 = (unsigned)wf < (unsigned)Ww;
            const int i = d0 * HW + h0 * Ww + w0;
            if (pd0 & ph0 & pw0) v000 = img[i];
            if (pd0 & ph0 & pw1) v001 = img[i + 1];
            if (pd0 & ph1 & pw0) v010 = img[i + Ww];
            if (pd0 & ph1 & pw1) v011 = img[i + Ww + 1];
            if (pd1 & ph0 & pw0) v100 = img[i + HW];
            if (pd1 & ph0 & pw1) v101 = img[i + HW + 1];
            if (pd1 & ph1 & pw0) v110 = img[i + HW + Ww];
            if (pd1 & ph1 & pw1) v111 = img[i + HW + Ww + 1];
        }

        // trilinear lerp: w, then h, then d
        const float a00 = v000 + fw * (v001 - v000);
        const float a01 = v010 + fw * (v011 - v010);
        const float a10 = v100 + fw * (v101 - v100);
        const float a11 = v110 + fw * (v111 - v110);

        const float b0 = a00 + fh * (a01 - a00);
        const float b1 = a10 + fh * (a11 - a10);

        out[g] = b0 + fd * (b1 - b0);
    }
}

} // namespace

extern "C" void kernel_launch(void* const* d_in, const int* in_sizes, int n_in,
                              void* d_out, int out_size)
{
    const float* img = (const float*)d_in[0];
    const float* off = (const float*)d_in[1];
    float* out = (float*)d_out;

    dim3 grid(Ww / TW, Hh / TH, Dd / TD);   // (7, 12, 20) — exact
    st3d_tiled_kernel<<<grid, NTHREADS>>>(img, off, out);
}

// round 4
// speedup vs baseline: 1.1228x; 1.1228x over previous
#include <cuda_runtime.h>
#include <cuda_bf16.h>

namespace {

constexpr int Dd = 160;
constexpr int Hh = 192;
constexpr int Ww = 224;
constexpr int HW = Hh * Ww;        // 43008
constexpr int N  = Dd * HW;        // 6881280

// tile: 4 x 8 x 32 outputs per block
constexpr int TD = 4, TH = 8, TW = 32;
// halos: d/h lo=4 hi=3 (N(0,1) jitter, asymmetric because floor tap = x-1+floor(j));
// w staged [W0-8, W0+40) for float4 alignment
constexpr int MLO = 4;
constexpr int SD = 11;             // TD + 4 + 3
constexpr int SH = 15;             // TH + 4 + 3
constexpr int SROW   = 48;         // floats per staged w-row (12 float4)
constexpr int SSLICE = SH * SROW;  // 720  (≡16 mod 32 — de-aliases banks)
constexpr int STOT   = SD * SSLICE;// 7920 floats = 31680 B  → 3 blocks/SM
constexpr int NF4    = SD * SH * (SROW / 4);  // 1980 float4 stage ops
constexpr int NTHREADS = 256;

__global__ __launch_bounds__(NTHREADS)
void st3d_kernel(const float* __restrict__ img,   // (160,192,224) fp32
                 const float* __restrict__ off,   // (3,160,192,224) fp32
                 float* __restrict__ out)         // (160,192,224) fp32
{
    __shared__ float smem[STOT];

    const int tid  = threadIdx.x;
    const int lane = tid & 31;
    const int warp = tid >> 5;

    const int D0 = blockIdx.z * TD;
    const int H0 = blockIdx.y * TH;
    const int W0 = blockIdx.x * TW;
    const int d_org = D0 - MLO;
    const int h_org = H0 - MLO;
    const int w_org = W0 - 8;

    // ---- stage tile (+halo) as float4, branchless zero-fill outside volume ----
    // every 4-aligned w-segment is fully inside or fully outside (224 % 4 == 0)
    float4* smem4 = reinterpret_cast<float4*>(smem);
    #pragma unroll 2
    for (int idx = tid; idx < NF4; idx += NTHREADS) {
        const int row = idx / 12;           // 12 float4 per row
        const int q   = idx - row * 12;
        const int sd  = row / SH;
        const int sh  = row - sd * SH;
        const int gd  = d_org + sd;
        const int gh  = h_org + sh;
        const int gw  = w_org + 4 * q;
        float4 v = make_float4(0.f, 0.f, 0.f, 0.f);
        if ((unsigned)gd < (unsigned)Dd && (unsigned)gh < (unsigned)Hh &&
            (unsigned)gw < (unsigned)Ww)
            v = *reinterpret_cast<const float4*>(img + gd * HW + gh * Ww + gw);
        smem4[sd * (SSLICE / 4) + sh * (SROW / 4) + q] = v;
    }
    __syncthreads();

    // ---- each warp: one (d,h) row, lane = w; 4 rows per warp ----
    #pragma unroll
    for (int rr = warp; rr < TD * TH; rr += NTHREADS / 32) {
        const int dl = rr >> 3;          // TH = 8
        const int hl = rr & 7;
        const int d = D0 + dl;
        const int h = H0 + hl;
        const int w = W0 + lane;
        const int g = d * HW + h * Ww + w;

        const float dDv = __ldg(off + g);
        const float dHv = __ldg(off + N + g);
        const float dWv = __ldg(off + 2 * N + g);

        // padded-space coords (+1 pad shift per reference)
        const float Dup = dDv + (float)(d + 1);
        const float Hup = dHv + (float)(h + 1);
        const float Wup = dWv + (float)(w + 1);

        const int df = __float2int_rd(Dup);
        const int hf = __float2int_rd(Hup);
        const int wf = __float2int_rd(Wup);

        const float fd = Dup - (float)df;
        const float fh = Hup - (float)hf;
        const float fw = Wup - (float)wf;

        // data-space floor-tap indices
        const int d0 = df - 1, h0 = hf - 1, w0 = wf - 1;

        // staged-local coords
        const int sd0 = d0 - d_org;
        const int sh0 = h0 - h_org;
        const int sw0 = w0 - w_org;

        float v000, v001, v010, v011, v100, v101, v110, v111;

        if ((unsigned)sd0 < (unsigned)(SD - 1) &&
            (unsigned)sh0 < (unsigned)(SH - 1) &&
            (unsigned)sw0 < (unsigned)(SROW - 1)) {
            // fast path: all 8 taps staged (volume boundary = zeros in smem)
            const float* ps = smem + sd0 * SSLICE + sh0 * SROW + sw0;
            v000 = ps[0];
            v001 = ps[1];
            v010 = ps[SROW];
            v011 = ps[SROW + 1];
            v100 = ps[SSLICE];
            v101 = ps[SSLICE + 1];
            v110 = ps[SSLICE + SROW];
            v111 = ps[SSLICE + SROW + 1];
        } else {
            // rare fallback (~0.1% of lanes): gather from global
            v000 = v001 = v010 = v011 = v100 = v101 = v110 = v111 = 0.f;
            const bool pd0 = (unsigned)d0 < (unsigned)Dd;
            const bool pd1 = (unsigned)df < (unsigned)Dd;
            const bool ph0 = (unsigned)h0 < (unsigned)Hh;
            const bool ph1 = (unsigned)hf < (unsigned)Hh;
            const bool pw0 = (unsigned)w0 < (unsigned)Ww;
            const bool pw1 = (unsigned)wf < (unsigned)Ww;
            const int i = d0 * HW + h0 * Ww + w0;
            if (pd0 & ph0 & pw0) v000 = img[i];
            if (pd0 & ph0 & pw1) v001 = img[i + 1];
            if (pd0 & ph1 & pw0) v010 = img[i + Ww];
            if (pd0 & ph1 & pw1) v011 = img[i + Ww + 1];
            if (pd1 & ph0 & pw0) v100 = img[i + HW];
            if (pd1 & ph0 & pw1) v101 = img[i + HW + 1];
            if (pd1 & ph1 & pw0) v110 = img[i + HW + Ww];
            if (pd1 & ph1 & pw1) v111 = img[i + HW + Ww + 1];
        }

        // trilinear lerp: w, then h, then d
        const float a00 = v000 + fw * (v001 - v000);
        const float a01 = v010 + fw * (v011 - v010);
        const float a10 = v100 + fw * (v101 - v100);
        const float a11 = v110 + fw * (v111 - v110);

        const float b0 = a00 + fh * (a01 - a00);
        const float b1 = a10 + fh * (a11 - a10);

        out[g] = b0 + fd * (b1 - b0);
    }
}

} // namespace

extern "C" void kernel_launch(void* const* d_in, const int* in_sizes, int n_in,
                              void* d_out, int out_size)
{
    const float* img = (const float*)d_in[0];
    const float* off = (const float*)d_in[1];
    float* out = (float*)d_out;

    dim3 grid(Ww / TW, Hh / TH, Dd / TD);   // (7, 24, 40) — exact
    st3d_kernel<<<grid, NTHREADS>>>(img, off, out);
}

// round 7
// speedup vs baseline: 1.3879x; 1.2361x over previous
#include <cuda_runtime.h>
#include <cuda_bf16.h>

namespace {

constexpr int Dd = 160;
constexpr int Hh = 192;
constexpr int Ww = 224;
constexpr int HW = Hh * Ww;        // 43008
constexpr int N  = Dd * HW;        // 6881280

// tile: 4 x 8 x 32 outputs per block (4096)
constexpr int TD = 4, TH = 8, TW = 32;
constexpr int MLO = 4;             // d/h halo: lo=4, hi=3
constexpr int SD = 11;             // TD + 7
constexpr int SH = 15;             // TH + 7
constexpr int SROW   = 48;         // staged floats per w-row (12 float4), w in [W0-8, W0+40)
constexpr int SSLICE = SH * SROW;  // 720 (≡16 mod 32 — de-aliases banks across h)
constexpr int STOT   = SD * SSLICE;// 7920 floats = 31680 B → 3 blocks/SM (smem-limited)
constexpr int NF4    = SD * SH * (SROW / 4);  // 1980 float4 stage ops
constexpr int NTHREADS = 256;

__global__ __launch_bounds__(NTHREADS)
void st3d_kernel(const float* __restrict__ img,   // (160,192,224) fp32
                 const float* __restrict__ off,   // (3,160,192,224) fp32
                 float* __restrict__ out)         // (160,192,224) fp32
{
    __shared__ float smem[STOT];

    const int tid  = threadIdx.x;
    const int lane = tid & 31;
    const int warp = tid >> 5;

    const int D0 = blockIdx.z * TD;
    const int H0 = blockIdx.y * TH;
    const int W0 = blockIdx.x * TW;
    const int d_org = D0 - MLO;
    const int h_org = H0 - MLO;
    const int w_org = W0 - 8;

    // warp -> one h row; thread covers all TD depth rows at (h, w)
    const int h = H0 + warp;        // TH == warps per block
    const int w = W0 + lane;

    // ---- issue ALL 12 offset loads up front (latency hidden behind staging) ----
    float oD[TD], oH[TD], oW[TD];
    #pragma unroll
    for (int k = 0; k < TD; k++) {
        const int g = (D0 + k) * HW + h * Ww + w;
        oD[k] = __ldg(off + g);
        oH[k] = __ldg(off + N + g);
        oW[k] = __ldg(off + 2 * N + g);
    }

    // ---- stage tile (+halo) as float4, branchless zero-fill outside volume ----
    // every 4-aligned w-segment is fully inside or fully outside (224 % 4 == 0)
    float4* smem4 = reinterpret_cast<float4*>(smem);
    #pragma unroll 2
    for (int idx = tid; idx < NF4; idx += NTHREADS) {
        const int row = idx / 12;
        const int q   = idx - row * 12;
        const int sd  = row / SH;
        const int sh  = row - sd * SH;
        const int gd  = d_org + sd;
        const int gh  = h_org + sh;
        const int gw  = w_org + 4 * q;
        float4 v = make_float4(0.f, 0.f, 0.f, 0.f);
        if ((unsigned)gd < (unsigned)Dd && (unsigned)gh < (unsigned)Hh &&
            (unsigned)gw < (unsigned)Ww)
            v = *reinterpret_cast<const float4*>(img + gd * HW + gh * Ww + gw);
        smem4[sd * (SSLICE / 4) + sh * (SROW / 4) + q] = v;
    }
    __syncthreads();

    // ---- fully unrolled 4-way compute: scheduler interleaves 32 LDS + 4 lerp trees ----
    #pragma unroll
    for (int k = 0; k < TD; k++) {
        const int d = D0 + k;
        const int g = d * HW + h * Ww + w;

        const float Dup = oD[k] + (float)(d + 1);
        const float Hup = oH[k] + (float)(h + 1);
        const float Wup = oW[k] + (float)(w + 1);

        const int df = __float2int_rd(Dup);
        const int hf = __float2int_rd(Hup);
        const int wf = __float2int_rd(Wup);

        const float fd = Dup - (float)df;
        const float fh = Hup - (float)hf;
        const float fw = Wup - (float)wf;

        const int d0 = df - 1, h0 = hf - 1, w0 = wf - 1;

        const int sd0 = d0 - d_org;
        const int sh0 = h0 - h_org;
        const int sw0 = w0 - w_org;

        float v000, v001, v010, v011, v100, v101, v110, v111;

        if ((unsigned)sd0 < (unsigned)(SD - 1) &&
            (unsigned)sh0 < (unsigned)(SH - 1) &&
            (unsigned)sw0 < (unsigned)(SROW - 1)) {
            // fast path: all 8 taps staged (volume boundary = zeros in smem)
            const float* ps = smem + sd0 * SSLICE + sh0 * SROW + sw0;
            v000 = ps[0];
            v001 = ps[1];
            v010 = ps[SROW];
            v011 = ps[SROW + 1];
            v100 = ps[SSLICE];
            v101 = ps[SSLICE + 1];
            v110 = ps[SSLICE + SROW];
            v111 = ps[SSLICE + SROW + 1];
        } else {
            // rare fallback (~0.1% of lanes): gather from global
            v000 = v001 = v010 = v011 = v100 = v101 = v110 = v111 = 0.f;
            const bool pd0 = (unsigned)d0 < (unsigned)Dd;
            const bool pd1 = (unsigned)df < (unsigned)Dd;
            const bool ph0 = (unsigned)h0 < (unsigned)Hh;
            const bool ph1 = (unsigned)hf < (unsigned)Hh;
            const bool pw0 = (unsigned)w0 < (unsigned)Ww;
            const bool pw1 = (unsigned)wf < (unsigned)Ww;
            const int i = d0 * HW + h0 * Ww + w0;
            if (pd0 & ph0 & pw0) v000 = img[i];
            if (pd0 & ph0 & pw1) v001 = img[i + 1];
            if (pd0 & ph1 & pw0) v010 = img[i + Ww];
            if (pd0 & ph1 & pw1) v011 = img[i + Ww + 1];
            if (pd1 & ph0 & pw0) v100 = img[i + HW];
            if (pd1 & ph0 & pw1) v101 = img[i + HW + 1];
            if (pd1 & ph1 & pw0) v110 = img[i + HW + Ww];
            if (pd1 & ph1 & pw1) v111 = img[i + HW + Ww + 1];
        }

        const float a00 = v000 + fw * (v001 - v000);
        const float a01 = v010 + fw * (v011 - v010);
        const float a10 = v100 + fw * (v101 - v100);
        const float a11 = v110 + fw * (v111 - v110);

        const float b0 = a00 + fh * (a01 - a00);
        const float b1 = a10 + fh * (a11 - a10);

        out[g] = b0 + fd * (b1 - b0);
    }
}

} // namespace

extern "C" void kernel_launch(void* const* d_in, const int* in_sizes, int n_in,
                              void* d_out, int out_size)
{
    const float* img = (const float*)d_in[0];
    const float* off = (const float*)d_in[1];
    float* out = (float*)d_out;

    dim3 grid(Ww / TW, Hh / TH, Dd / TD);   // (7, 24, 40) — exact
    st3d_kernel<<<grid, NTHREADS>>>(img, off, out);
}

// round 8
// speedup vs baseline: 1.6374x; 1.1798x over previous
#include <cuda_runtime.h>
#include <cuda_bf16.h>
#include <cstdint>

namespace {

constexpr int Dd = 160;
constexpr int Hh = 192;
constexpr int Ww = 224;
constexpr int HW = Hh * Ww;        // 43008
constexpr int N  = Dd * HW;        // 6881280

// tile: 4 x 8 x 32 outputs per block (1024)
constexpr int TD = 4, TH = 8, TW = 32;
constexpr int MLO = 4;             // d/h halo: lo=4, hi=3
constexpr int SD = 11;             // TD + 7
constexpr int SH = 15;             // TH + 7
constexpr int SROW   = 48;         // staged floats per w-row, w in [W0-8, W0+40)
constexpr int SSLICE = SH * SROW;  // 720
constexpr int STOT   = SD * SSLICE;// 7920 floats = 31680 B
constexpr int NROWS  = SD * SH;    // 165 staged (d,h) rows
constexpr int NTHREADS = 256;

__device__ __forceinline__ uint32_t smem_u32(const void* p) {
    return (uint32_t)__cvta_generic_to_shared(p);
}

__global__ __launch_bounds__(NTHREADS)
void st3d_kernel(const float* __restrict__ img,   // (160,192,224) fp32
                 const float* __restrict__ off,   // (3,160,192,224) fp32
                 float* __restrict__ out)         // (160,192,224) fp32
{
    __shared__ __align__(128) float smem[STOT];
    __shared__ __align__(8) uint64_t mbar;

    const int tid  = threadIdx.x;
    const int lane = tid & 31;
    const int warp = tid >> 5;

    const int D0 = blockIdx.z * TD;
    const int H0 = blockIdx.y * TH;
    const int W0 = blockIdx.x * TW;
    const int d_org = D0 - MLO;
    const int h_org = H0 - MLO;
    const int w_org = W0 - 8;

    const uint32_t mb = smem_u32(&mbar);

    if (tid == 0) {
        asm volatile("mbarrier.init.shared.b64 [%0], 1;" :: "r"(mb) : "memory");
    }
    __syncthreads();

    // w clip (same for all rows of this block): boundaries are multiples of 8 floats
    const int wlo  = w_org < 0 ? 0 : w_org;
    const int whi  = (w_org + SROW) > Ww ? Ww : (w_org + SROW);
    const int head = wlo - w_org;               // 0 or 8 floats
    const int rowbytes = (whi - wlo) * 4;       // 192 or 160 B (mult of 16)

    if (tid == 0) {
        // expected bytes = valid rows * bytes per row
        const int dlo = d_org < 0 ? 0 : d_org;
        const int dhi = (d_org + SD) > Dd ? Dd : (d_org + SD);
        const int hlo = h_org < 0 ? 0 : h_org;
        const int hhi = (h_org + SH) > Hh ? Hh : (h_org + SH);
        const uint32_t expect = (uint32_t)((dhi - dlo) * (hhi - hlo) * rowbytes);
        asm volatile("mbarrier.arrive.expect_tx.shared.b64 _, [%0], %1;"
                     :: "r"(mb), "r"(expect) : "memory");
    }

    // warp -> one h row; thread covers all TD depth rows at (h, w)
    const int h = H0 + warp;        // TH == warps per block
    const int w = W0 + lane;

    // ---- hoist all 12 offset loads (DRAM latency overlaps the bulk fill) ----
    float oD[TD], oH[TD], oW[TD];
    #pragma unroll
    for (int k = 0; k < TD; k++) {
        const int g = (D0 + k) * HW + h * Ww + w;
        oD[k] = __ldg(off + g);
        oH[k] = __ldg(off + N + g);
        oW[k] = __ldg(off + 2 * N + g);
    }

    __syncthreads();   // expect_tx posted before any completion can close the phase

    // ---- stage via cp.async.bulk: one 192B (or 160B) DMA per valid (d,h) row ----
    if (tid < NROWS) {
        const int sd = tid / SH;
        const int sh = tid - sd * SH;
        const int gd = d_org + sd;
        const int gh = h_org + sh;
        float* dstrow = smem + (sd * SH + sh) * SROW;

        if ((unsigned)gd < (unsigned)Dd && (unsigned)gh < (unsigned)Hh) {
            // zero the w head/tail (edge blocks only; 0 or 8 floats each)
            for (int i = 0; i < head; i++) dstrow[i] = 0.f;
            for (int i = head + (rowbytes >> 2); i < SROW; i++) dstrow[i] = 0.f;
            const float* src = img + gd * HW + gh * Ww + wlo;
            asm volatile(
                "cp.async.bulk.shared::cluster.global.mbarrier::complete_tx::bytes "
                "[%0], [%1], %2, [%3];"
                :: "r"(smem_u32(dstrow + head)), "l"(src),
                   "r"((uint32_t)rowbytes), "r"(mb)
                : "memory");
        } else {
            // whole row outside volume: zero-fill (edge blocks only)
            #pragma unroll 4
            for (int i = 0; i < SROW; i++) dstrow[i] = 0.f;
        }
    }
    __syncthreads();   // makes the STS zero-fills visible to all threads

    // wait for all bulk DMAs (acquire orders TMA data before our LDS reads)
    {
        uint32_t done;
        asm volatile(
            "{\n\t"
            ".reg .pred p;\n\t"
            "mbarrier.try_wait.parity.acquire.cta.shared::cta.b64 p, [%1], 0;\n\t"
            "selp.b32 %0, 1, 0, p;\n\t"
            "}" : "=r"(done) : "r"(mb) : "memory");
        if (!done) {
            asm volatile(
                "{\n\t"
                ".reg .pred P1;\n\t"
                "WL_%=:\n\t"
                "mbarrier.try_wait.parity.acquire.cta.shared::cta.b64 P1, [%0], 0, 0x989680;\n\t"
                "@P1 bra.uni WD_%=;\n\t"
                "bra.uni WL_%=;\n\t"
                "WD_%=:\n\t"
                "}" :: "r"(mb) : "memory");
        }
    }

    // ---- fully unrolled 4-way compute: 32 LDS + 4 lerp trees interleaved ----
    #pragma unroll
    for (int k = 0; k < TD; k++) {
        const int d = D0 + k;
        const int g = d * HW + h * Ww + w;

        const float Dup = oD[k] + (float)(d + 1);
        const float Hup = oH[k] + (float)(h + 1);
        const float Wup = oW[k] + (float)(w + 1);

        const int df = __float2int_rd(Dup);
        const int hf = __float2int_rd(Hup);
        const int wf = __float2int_rd(Wup);

        const float fd = Dup - (float)df;
        const float fh = Hup - (float)hf;
        const float fw = Wup - (float)wf;

        const int d0 = df - 1, h0 = hf - 1, w0 = wf - 1;

        const int sd0 = d0 - d_org;
        const int sh0 = h0 - h_org;
        const int sw0 = w0 - w_org;

        float v000, v001, v010, v011, v100, v101, v110, v111;

        if ((unsigned)sd0 < (unsigned)(SD - 1) &&
            (unsigned)sh0 < (unsigned)(SH - 1) &&
            (unsigned)sw0 < (unsigned)(SROW - 1)) {
            // fast path: all 8 taps staged (out-of-volume = zeros in smem)
            const float* ps = smem + sd0 * SSLICE + sh0 * SROW + sw0;
            v000 = ps[0];
            v001 = ps[1];
            v010 = ps[SROW];
            v011 = ps[SROW + 1];
            v100 = ps[SSLICE];
            v101 = ps[SSLICE + 1];
            v110 = ps[SSLICE + SROW];
            v111 = ps[SSLICE + SROW + 1];
        } else {
            // rare fallback (~0.1% of lanes): gather from global
            v000 = v001 = v010 = v011 = v100 = v101 = v110 = v111 = 0.f;
            const bool pd0 = (unsigned)d0 < (unsigned)Dd;
            const bool pd1 = (unsigned)df < (unsigned)Dd;
            const bool ph0 = (unsigned)h0 < (unsigned)Hh;
            const bool ph1 = (unsigned)hf < (unsigned)Hh;
            const bool pw0 = (unsigned)w0 < (unsigned)Ww;
            const bool pw1 = (unsigned)wf < (unsigned)Ww;
            const int i = d0 * HW + h0 * Ww + w0;
            if (pd0 & ph0 & pw0) v000 = img[i];
            if (pd0 & ph0 & pw1) v001 = img[i + 1];
            if (pd0 & ph1 & pw0) v010 = img[i + Ww];
            if (pd0 & ph1 & pw1) v011 = img[i + Ww + 1];
            if (pd1 & ph0 & pw0) v100 = img[i + HW];
            if (pd1 & ph0 & pw1) v101 = img[i + HW + 1];
            if (pd1 & ph1 & pw0) v110 = img[i + HW + Ww];
            if (pd1 & ph1 & pw1) v111 = img[i + HW + Ww + 1];
        }

        const float a00 = v000 + fw * (v001 - v000);
        const float a01 = v010 + fw * (v011 - v010);
        const float a10 = v100 + fw * (v101 - v100);
        const float a11 = v110 + fw * (v111 - v110);

        const float b0 = a00 + fh * (a01 - a00);
        const float b1 = a10 + fh * (a11 - a10);

        out[g] = b0 + fd * (b1 - b0);
    }
}

} // namespace

extern "C" void kernel_launch(void* const* d_in, const int* in_sizes, int n_in,
                              void* d_out, int out_size)
{
    const float* img = (const float*)d_in[0];
    const float* off = (const float*)d_in[1];
    float* out = (float*)d_out;

    dim3 grid(Ww / TW, Hh / TH, Dd / TD);   // (7, 24, 40) — exact
    st3d_kernel<<<grid, NTHREADS>>>(img, off, out);
}

// round 9
// speedup vs baseline: 1.6741x; 1.0224x over previous
#include <cuda_runtime.h>
#include <cuda_bf16.h>
#include <cstdint>

namespace {

constexpr int Dd = 160;
constexpr int Hh = 192;
constexpr int Ww = 224;
constexpr int HW = Hh * Ww;        // 43008
constexpr int N  = Dd * HW;        // 6881280

// tile: 4 x 8 x 32 outputs per block (1024)
constexpr int TD = 4, TH = 8, TW = 32;
constexpr int MLO = 4;             // d/h halo: lo=4, hi=3
constexpr int SD = 11;             // TD + 7
constexpr int SH = 15;             // TH + 7
constexpr int SROW   = 48;         // staged floats per w-row, w in [W0-8, W0+40)
constexpr int SSLICE = SH * SROW;  // 720
constexpr int STOT   = SD * SSLICE;// 7920 floats = 31680 B
constexpr int NROWS  = SD * SH;    // 165 staged (d,h) rows
constexpr int NTHREADS = 256;

__device__ __forceinline__ uint32_t smem_u32(const void* p) {
    return (uint32_t)__cvta_generic_to_shared(p);
}

__global__ __launch_bounds__(NTHREADS)
void st3d_kernel(const float* __restrict__ img,   // (160,192,224) fp32
                 const float* __restrict__ off,   // (3,160,192,224) fp32
                 float* __restrict__ out)         // (160,192,224) fp32
{
    __shared__ __align__(128) float smem[STOT];
    __shared__ __align__(8) uint64_t mbar;

    const int tid  = threadIdx.x;
    const int lane = tid & 31;
    const int warp = tid >> 5;

    const int D0 = blockIdx.z * TD;
    const int H0 = blockIdx.y * TH;
    const int W0 = blockIdx.x * TW;
    const int d_org = D0 - MLO;
    const int h_org = H0 - MLO;
    const int w_org = W0 - 8;

    // warp -> one h row; thread covers all TD depth rows at (h, w)
    const int h = H0 + warp;        // TH == warps per block
    const int w = W0 + lane;
    const int base_g = D0 * HW + h * Ww + w;

    // ---- hoist all 12 offset loads first (DRAM latency overlaps everything) ----
    const float* offD = off + base_g;
    const float* offH = off + N + base_g;
    const float* offW = off + 2 * N + base_g;
    float oD[TD], oH[TD], oW[TD];
    #pragma unroll
    for (int k = 0; k < TD; k++) {
        oD[k] = __ldg(offD + k * HW);   // immediate offsets (k*HW*4 < 16MB)
        oH[k] = __ldg(offH + k * HW);
        oW[k] = __ldg(offW + k * HW);
    }

    const uint32_t mb = smem_u32(&mbar);

    // w clip (same for all rows of this block): boundaries are multiples of 8 floats
    const int wlo  = w_org < 0 ? 0 : w_org;
    const int whi  = (w_org + SROW) > Ww ? Ww : (w_org + SROW);
    const int head = wlo - w_org;               // 0 or 8 floats
    const int rowbytes = (whi - wlo) * 4;       // 192 or 160 B (mult of 16)

    if (tid == 0) {
        asm volatile("mbarrier.init.shared.b64 [%0], 1;" :: "r"(mb) : "memory");
        const int dlo = d_org < 0 ? 0 : d_org;
        const int dhi = (d_org + SD) > Dd ? Dd : (d_org + SD);
        const int hlo = h_org < 0 ? 0 : h_org;
        const int hhi = (h_org + SH) > Hh ? Hh : (h_org + SH);
        const uint32_t expect = (uint32_t)((dhi - dlo) * (hhi - hlo) * rowbytes);
        asm volatile("mbarrier.arrive.expect_tx.shared.b64 _, [%0], %1;"
                     :: "r"(mb), "r"(expect) : "memory");
    }
    __syncthreads();   // init+expect visible before any TMA references the barrier

    // ---- stage via cp.async.bulk: one 192B (or 160B) DMA per valid (d,h) row ----
    if (tid < NROWS) {
        const int sd = tid / SH;
        const int sh = tid - sd * SH;
        const int gd = d_org + sd;
        const int gh = h_org + sh;
        float* dstrow = smem + (sd * SH + sh) * SROW;

        if ((unsigned)gd < (unsigned)Dd && (unsigned)gh < (unsigned)Hh) {
            for (int i = 0; i < head; i++) dstrow[i] = 0.f;
            for (int i = head + (rowbytes >> 2); i < SROW; i++) dstrow[i] = 0.f;
            const float* src = img + gd * HW + gh * Ww + wlo;
            asm volatile(
                "cp.async.bulk.shared::cluster.global.mbarrier::complete_tx::bytes "
                "[%0], [%1], %2, [%3];"
                :: "r"(smem_u32(dstrow + head)), "l"(src),
                   "r"((uint32_t)rowbytes), "r"(mb)
                : "memory");
        } else {
            #pragma unroll 4
            for (int i = 0; i < SROW; i++) dstrow[i] = 0.f;
        }
    }
    __syncthreads();   // zero-fill STS visible to all threads

    // wait for all bulk DMAs (acquire orders TMA data before our LDS reads)
    {
        uint32_t done;
        asm volatile(
            "{\n\t"
            ".reg .pred p;\n\t"
            "mbarrier.try_wait.parity.acquire.cta.shared::cta.b64 p, [%1], 0;\n\t"
            "selp.b32 %0, 1, 0, p;\n\t"
            "}" : "=r"(done) : "r"(mb) : "memory");
        if (!done) {
            asm volatile(
                "{\n\t"
                ".reg .pred P1;\n\t"
                "WL_%=:\n\t"
                "mbarrier.try_wait.parity.acquire.cta.shared::cta.b64 P1, [%0], 0, 0x989680;\n\t"
                "@P1 bra.uni WD_%=;\n\t"
                "bra.uni WL_%=;\n\t"
                "WD_%=:\n\t"
                "}" :: "r"(mb) : "memory");
        }
    }

    // precomputed shifts: sX0 = floor(coord_up) - (1 + org)
    const int cd = 1 + d_org;
    const int ch = 1 + h_org;
    const int cw = 1 + w_org;
    float* outp = out + base_g;

    // ---- fully unrolled 4-way compute: 32 LDS + 4 lerp trees interleaved ----
    #pragma unroll
    for (int k = 0; k < TD; k++) {
        const int d = D0 + k;

        const float Dup = oD[k] + (float)(d + 1);
        const float Hup = oH[k] + (float)(h + 1);
        const float Wup = oW[k] + (float)(w + 1);

        const int df = __float2int_rd(Dup);
        const int hf = __float2int_rd(Hup);
        const int wf = __float2int_rd(Wup);

        const float fd = Dup - (float)df;
        const float fh = Hup - (float)hf;
        const float fw = Wup - (float)wf;

        // staged-local floor-tap coords (fallback reconstructs globals from these)
        const int sd0 = df - cd;
        const int sh0 = hf - ch;
        const int sw0 = wf - cw;

        float v000, v001, v010, v011, v100, v101, v110, v111;

        if ((unsigned)sd0 < (unsigned)(SD - 1) &&
            (unsigned)sh0 < (unsigned)(SH - 1) &&
            (unsigned)sw0 < (unsigned)(SROW - 1)) {
            // fast path: all 8 taps staged (out-of-volume = zeros in smem)
            const float* ps = smem + sd0 * SSLICE + sh0 * SROW + sw0;
            v000 = ps[0];
            v001 = ps[1];
            v010 = ps[SROW];
            v011 = ps[SROW + 1];
            v100 = ps[SSLICE];
            v101 = ps[SSLICE + 1];
            v110 = ps[SSLICE + SROW];
            v111 = ps[SSLICE + SROW + 1];
        } else {
            // rare fallback (~0.1% of lanes): gather from global
            v000 = v001 = v010 = v011 = v100 = v101 = v110 = v111 = 0.f;
            const int d0 = sd0 + d_org, h0 = sh0 + h_org, w0 = sw0 + w_org;
            const bool pd0 = (unsigned)d0 < (unsigned)Dd;
            const bool pd1 = (unsigned)(d0 + 1) < (unsigned)Dd;
            const bool ph0 = (unsigned)h0 < (unsigned)Hh;
            const bool ph1 = (unsigned)(h0 + 1) < (unsigned)Hh;
            const bool pw0 = (unsigned)w0 < (unsigned)Ww;
            const bool pw1 = (unsigned)(w0 + 1) < (unsigned)Ww;
            const int i = d0 * HW + h0 * Ww + w0;
            if (pd0 & ph0 & pw0) v000 = img[i];
            if (pd0 & ph0 & pw1) v001 = img[i + 1];
            if (pd0 & ph1 & pw0) v010 = img[i + Ww];
            if (pd0 & ph1 & pw1) v011 = img[i + Ww + 1];
            if (pd1 & ph0 & pw0) v100 = img[i + HW];
            if (pd1 & ph0 & pw1) v101 = img[i + HW + 1];
            if (pd1 & ph1 & pw0) v110 = img[i + HW + Ww];
            if (pd1 & ph1 & pw1) v111 = img[i + HW + Ww + 1];
        }

        const float a00 = v000 + fw * (v001 - v000);
        const float a01 = v010 + fw * (v011 - v010);
        const float a10 = v100 + fw * (v101 - v100);
        const float a11 = v110 + fw * (v111 - v110);

        const float b0 = a00 + fh * (a01 - a00);
        const float b1 = a10 + fh * (a11 - a10);

        outp[k * HW] = b0 + fd * (b1 - b0);
    }
}

} // namespace

extern "C" void kernel_launch(void* const* d_in, const int* in_sizes, int n_in,
                              void* d_out, int out_size)
{
    const float* img = (const float*)d_in[0];
    const float* off = (const float*)d_in[1];
    float* out = (float*)d_out;

    // widen the smem carveout so ~6 blocks (48 warps) can co-reside per SM
    cudaFuncSetAttribute(st3d_kernel,
                         cudaFuncAttributePreferredSharedMemoryCarveout, 100);

    dim3 grid(Ww / TW, Hh / TH, Dd / TD);   // (7, 24, 40) — exact
    st3d_kernel<<<grid, NTHREADS>>>(img, off, out);
}